// round 6
// baseline (speedup 1.0000x reference)
#include <cuda_runtime.h>
#include <math.h>

#define MAXN 50000
#define MAXE 800000
#define C_IN 64
#define C_OUT 64
#define HEADS 4
#define HC 256   // HEADS*C_OUT

// ---------------- scratch (static device globals; no allocation) ----------------
__device__ float  g_XH[MAXN * HC];          // 51.2 MB
__device__ float  g_ALS[MAXN * HEADS];
__device__ float  g_ALD[MAXN * HEADS];
__device__ float  g_MMAX[MAXN * HEADS];
__device__ float  g_DEN[MAXN * HEADS];
__device__ float  g_EBUF[(MAXE + MAXN) * HEADS];
__device__ float  g_ACC[MAXN * C_OUT];
__device__ float  g_SAV1[MAXN * C_OUT];
__device__ float  g_H1[MAXN * C_OUT];
__device__ double g_BNS[128];
__device__ float  g_SCALE[64];
__device__ float  g_SHIFT[64];

// ---------------- helpers ----------------
__device__ __forceinline__ void atomicMaxF(float* addr, float v) {
    if (v >= 0.0f) atomicMax((int*)addr, __float_as_int(v));
    else           atomicMin((unsigned int*)addr, __float_as_uint(v));
}

// ---------------- GEMM: XH[N,256] = X[N,64] @ W[64,256] ----------------
__global__ void gemm_kernel(const float* __restrict__ X, const float* __restrict__ W, int N) {
    __shared__ float xs[64][65];
    __shared__ float ws[64][65];
    int m0 = blockIdx.x * 64;
    int j0 = blockIdx.y * 64;
    int tid = threadIdx.x;
    for (int i = tid; i < 64 * 64; i += 256) {
        int r = i >> 6, k = i & 63;
        int row = m0 + r;
        xs[r][k] = (row < N) ? X[row * 64 + k] : 0.0f;
        ws[r][k] = W[r * HC + j0 + k];   // ws[k][j]
    }
    __syncthreads();
    int tx = tid & 15, ty = tid >> 4;
    float acc[4][4];
#pragma unroll
    for (int i = 0; i < 4; i++)
#pragma unroll
        for (int j = 0; j < 4; j++) acc[i][j] = 0.0f;
#pragma unroll 8
    for (int k = 0; k < 64; k++) {
        float a[4], b[4];
#pragma unroll
        for (int i = 0; i < 4; i++) a[i] = xs[ty * 4 + i][k];
#pragma unroll
        for (int j = 0; j < 4; j++) b[j] = ws[k][tx * 4 + j];
#pragma unroll
        for (int i = 0; i < 4; i++)
#pragma unroll
            for (int j = 0; j < 4; j++) acc[i][j] += a[i] * b[j];
    }
#pragma unroll
    for (int i = 0; i < 4; i++) {
        int row = m0 + ty * 4 + i;
        if (row < N) {
#pragma unroll
            for (int j = 0; j < 4; j++)
                g_XH[row * HC + j0 + tx * 4 + j] = acc[i][j];
        }
    }
}

// ---------------- attention coefficients: one warp per node ----------------
__global__ void coef_kernel(const float* __restrict__ asrc, const float* __restrict__ adst, int N) {
    int warp = (blockIdx.x * blockDim.x + threadIdx.x) >> 5;
    int lane = threadIdx.x & 31;
    if (warp >= N) return;
    const float* row = g_XH + (size_t)warp * HC;
    float ps[4] = {0, 0, 0, 0}, pd[4] = {0, 0, 0, 0};
#pragma unroll
    for (int k = 0; k < 8; k++) {
        int c = lane + 32 * k;
        float v = row[c];
        ps[k >> 1] += v * asrc[c];
        pd[k >> 1] += v * adst[c];
    }
#pragma unroll
    for (int h = 0; h < 4; h++) {
        float s = ps[h], d = pd[h];
#pragma unroll
        for (int o = 16; o > 0; o >>= 1) {
            s += __shfl_xor_sync(0xffffffffu, s, o);
            d += __shfl_xor_sync(0xffffffffu, d, o);
        }
        if (lane == 0) { g_ALS[warp * 4 + h] = s; g_ALD[warp * 4 + h] = d; }
    }
}

// ---------------- per-layer init ----------------
__global__ void init_kernel(int N) {
    int i = blockIdx.x * blockDim.x + threadIdx.x;
    if (i < N * 4) { g_MMAX[i] = -INFINITY; g_DEN[i] = 0.0f; }
    if (i < N * 64) g_ACC[i] = 0.0f;
    if (i < 128) g_BNS[i] = 0.0;
}

// ---------------- edge pass 1: e = leakyrelu(als[src]+ald[dst]), segment max ----
// one thread per edge, all 4 heads via float4
__global__ void edge_max_kernel(const int* __restrict__ ESRC, const int* __restrict__ EDST,
                                int E, int N) {
    int eid = blockIdx.x * blockDim.x + threadIdx.x;
    if (eid >= E + N) return;
    int src, dst;
    if (eid < E) { src = ESRC[eid]; dst = EDST[eid]; }
    else         { src = dst = eid - E; }
    float4 s4 = *(const float4*)(g_ALS + src * 4);
    float4 d4 = *(const float4*)(g_ALD + dst * 4);
    float e0 = s4.x + d4.x; e0 = e0 > 0.0f ? e0 : 0.2f * e0;
    float e1 = s4.y + d4.y; e1 = e1 > 0.0f ? e1 : 0.2f * e1;
    float e2 = s4.z + d4.z; e2 = e2 > 0.0f ? e2 : 0.2f * e2;
    float e3 = s4.w + d4.w; e3 = e3 > 0.0f ? e3 : 0.2f * e3;
    *(float4*)(g_EBUF + (size_t)eid * 4) = make_float4(e0, e1, e2, e3);
    float* m = g_MMAX + dst * 4;
    atomicMaxF(m + 0, e0);
    atomicMaxF(m + 1, e1);
    atomicMaxF(m + 2, e2);
    atomicMaxF(m + 3, e3);
}

// ---------------- edge pass 2: p = exp(e - m), segment sum ----------------
__global__ void edge_exp_kernel(const int* __restrict__ EDST, int E, int N) {
    int eid = blockIdx.x * blockDim.x + threadIdx.x;
    if (eid >= E + N) return;
    int dst = (eid < E) ? EDST[eid] : (eid - E);
    float4 m4 = *(const float4*)(g_MMAX + dst * 4);
    float4 e4 = *(const float4*)(g_EBUF + (size_t)eid * 4);
    float p0 = __expf(e4.x - m4.x);
    float p1 = __expf(e4.y - m4.y);
    float p2 = __expf(e4.z - m4.z);
    float p3 = __expf(e4.w - m4.w);
    *(float4*)(g_EBUF + (size_t)eid * 4) = make_float4(p0, p1, p2, p3);
    float* d = g_DEN + dst * 4;
    atomicAdd(d + 0, p0);
    atomicAdd(d + 1, p1);
    atomicAdd(d + 2, p2);
    atomicAdd(d + 3, p3);
}

// ---------------- edge pass 3: scatter (head-mean fused, 64 floats/edge) --------
__global__ void edge_scatter_kernel(const int* __restrict__ ESRC, const int* __restrict__ EDST,
                                    int E, int N) {
    int t = blockIdx.x * blockDim.x + threadIdx.x;
    int eid = t >> 6;
    int c = t & 63;
    if (eid >= E + N) return;
    int src, dst;
    if (eid < E) { src = ESRC[eid]; dst = EDST[eid]; }
    else         { src = dst = eid - E; }
    float4 p4 = *(const float4*)(g_EBUF + (size_t)eid * 4);   // warp-uniform
    float4 d4 = *(const float4*)(g_DEN + dst * 4);            // warp-uniform
    float a0 = p4.x / (d4.x + 1e-16f);
    float a1 = p4.y / (d4.y + 1e-16f);
    float a2 = p4.z / (d4.z + 1e-16f);
    float a3 = p4.w / (d4.w + 1e-16f);
    const float* r = g_XH + (size_t)src * HC;
    float v = a0 * r[c] + a1 * r[64 + c] + a2 * r[128 + c] + a3 * r[192 + c];
    atomicAdd(&g_ACC[dst * 64 + c], 0.25f * v);
}

// ---------------- finalize: +bias, write saved, accumulate BN stats ----------
__global__ void finalize_stats_kernel(const float* __restrict__ bias, float* __restrict__ SAV, int N) {
    __shared__ float s1[64], s2[64];
    if (threadIdx.x < 64) { s1[threadIdx.x] = 0.0f; s2[threadIdx.x] = 0.0f; }
    __syncthreads();
    int c = threadIdx.x & 63;
    float bc = bias[c];
    float ls = 0.0f, lq = 0.0f;
    int total = N * 64;
    int stride = gridDim.x * blockDim.x;   // multiple of 64
    for (int i = blockIdx.x * blockDim.x + threadIdx.x; i < total; i += stride) {
        float v = g_ACC[i] + bc;
        SAV[i] = v;
        ls += v;
        lq += v * v;
    }
    atomicAdd(&s1[c], ls);
    atomicAdd(&s2[c], lq);
    __syncthreads();
    if (threadIdx.x < 64) {
        atomicAdd(&g_BNS[threadIdx.x], (double)s1[threadIdx.x]);
        atomicAdd(&g_BNS[64 + threadIdx.x], (double)s2[threadIdx.x]);
    }
}

// ---------------- BN parameter computation ----------------
__global__ void bn_param_kernel(const float* __restrict__ gamma, const float* __restrict__ beta, int N) {
    int c = threadIdx.x;
    if (c >= 64) return;
    double mean = g_BNS[c] / (double)N;
    double var = g_BNS[64 + c] / (double)N - mean * mean;
    float sc = gamma[c] * rsqrtf((float)(var + 1e-5));
    g_SCALE[c] = sc;
    g_SHIFT[c] = beta[c] - (float)mean * sc;
}

// ---------------- normalize + relu ----------------
__global__ void bn_relu_kernel(const float* __restrict__ SAV, float* __restrict__ OUT, int N) {
    int i = blockIdx.x * blockDim.x + threadIdx.x;
    if (i >= N * 64) return;
    int c = i & 63;
    float v = g_SCALE[c] * SAV[i] + g_SHIFT[c];
    OUT[i] = v > 0.0f ? v : 0.0f;
}

// ---------------- host launch ----------------
static void run_layer(const float* xin, const int* ESRC, const int* EDST,
                      const float* W, const float* asrc, const float* adst,
                      const float* bias, const float* gamma, const float* beta,
                      float* SAV, float* OUT, int N, int E) {
    dim3 gg((N + 63) / 64, 4);
    gemm_kernel<<<gg, 256>>>(xin, W, N);
    coef_kernel<<<(N * 32 + 255) / 256, 256>>>(asrc, adst, N);
    init_kernel<<<(N * 64 + 255) / 256, 256>>>(N);
    int totE = E + N;
    edge_max_kernel<<<(totE + 255) / 256, 256>>>(ESRC, EDST, E, N);
    edge_exp_kernel<<<(totE + 255) / 256, 256>>>(EDST, E, N);
    long long totSc = (long long)totE * 64;
    edge_scatter_kernel<<<(int)((totSc + 255) / 256), 256>>>(ESRC, EDST, E, N);
    finalize_stats_kernel<<<1024, 256>>>(bias, SAV, N);
    bn_param_kernel<<<1, 64>>>(gamma, beta, N);
    bn_relu_kernel<<<(N * 64 + 255) / 256, 256>>>(SAV, OUT, N);
}

extern "C" void kernel_launch(void* const* d_in, const int* in_sizes, int n_in,
                              void* d_out, int out_size) {
    const float* x  = (const float*)d_in[0];
    const int*   EI = (const int*)d_in[1];   // int32 (JAX x64 disabled downcasts int64)
    // d_in[2] = edge_weight (ignored, edge_dim=None)
    const float* W0 = (const float*)d_in[3];
    const float* as0 = (const float*)d_in[4];
    const float* ad0 = (const float*)d_in[5];
    const float* b0 = (const float*)d_in[6];
    const float* g0 = (const float*)d_in[7];
    const float* be0 = (const float*)d_in[8];
    const float* W1 = (const float*)d_in[9];
    const float* as1 = (const float*)d_in[10];
    const float* ad1 = (const float*)d_in[11];
    const float* b1 = (const float*)d_in[12];
    const float* g1 = (const float*)d_in[13];
    const float* be1 = (const float*)d_in[14];

    int N = in_sizes[0] / C_IN;
    int E = in_sizes[1] / 2;
    if (N > MAXN) N = MAXN;
    if (E > MAXE) E = MAXE;

    const int* ESRC = EI;        // edge_index[0]
    const int* EDST = EI + E;    // edge_index[1]

    float* out = (float*)d_out;           // [0 : N*64)        -> x (post bn+relu)
    float* saved = out + (size_t)N * 64;  // [N*64 : 2*N*64)   -> layer-2 pre-BN

    float* dSAV1;
    float* dH1;
    cudaGetSymbolAddress((void**)&dSAV1, g_SAV1);
    cudaGetSymbolAddress((void**)&dH1, g_H1);

    // layer 0
    run_layer(x, ESRC, EDST, W0, as0, ad0, b0, g0, be0, dSAV1, dH1, N, E);
    // layer 1: saved goes straight into d_out second half, normalized into first half
    run_layer(dH1, ESRC, EDST, W1, as1, ad1, b1, g1, be1, saved, out, N, E);
}

// round 7
// speedup vs baseline: 1.7829x; 1.7829x over previous
#include <cuda_runtime.h>
#include <math.h>

#define MAXN 50000
#define MAXE 800000
#define C_IN 64
#define C_OUT 64
#define HEADS 4
#define HC 256   // HEADS*C_OUT

// ---------------- scratch (static device globals; no allocation) ----------------
__device__ float  g_XH[MAXN * HC];          // 51.2 MB
__device__ float  g_ALS[MAXN * HEADS];
__device__ float  g_ALD[MAXN * HEADS];
__device__ float  g_EBUF[(MAXE + MAXN) * HEADS];   // p values in CSR order
__device__ float  g_SAV1[MAXN * C_OUT];
__device__ float  g_H1[MAXN * C_OUT];
__device__ double g_BNS[128];
__device__ float  g_SCALE[64];
__device__ float  g_SHIFT[64];
// CSR (built once per launch; structure shared by both layers)
__device__ int    g_DEG[MAXN];
__device__ int    g_ROWPTR[MAXN + 1];
__device__ int    g_CUR[MAXN];
__device__ int    g_CSRC[MAXE + MAXN];

// =====================================================================
// CSR build
// =====================================================================
__global__ void deg_init_kernel(int N) {
    int i = blockIdx.x * blockDim.x + threadIdx.x;
    if (i < N) g_DEG[i] = 1;   // self loop
}

__global__ void deg_count_kernel(const int* __restrict__ EDST, int E) {
    int e = blockIdx.x * blockDim.x + threadIdx.x;
    if (e < E) atomicAdd(&g_DEG[EDST[e]], 1);
}

// single-block exclusive scan over N degrees -> rowptr, cursor
__global__ void scan_kernel(int N) {
    __shared__ int sh[1024];
    __shared__ int carry;
    int t = threadIdx.x;
    if (t == 0) carry = 0;
    __syncthreads();
    for (int base = 0; base < N; base += 1024) {
        int i = base + t;
        int v = (i < N) ? g_DEG[i] : 0;
        sh[t] = v;
        __syncthreads();
        for (int o = 1; o < 1024; o <<= 1) {
            int add = (t >= o) ? sh[t - o] : 0;
            __syncthreads();
            sh[t] += add;
            __syncthreads();
        }
        int incl = sh[t];
        int excl = carry + incl - v;
        if (i < N) { g_ROWPTR[i] = excl; g_CUR[i] = excl; }
        __syncthreads();
        if (t == 0) carry += sh[1023];
        __syncthreads();
    }
    if (t == 0) g_ROWPTR[N] = carry;
}

__global__ void fill_kernel(const int* __restrict__ ESRC, const int* __restrict__ EDST,
                            int E, int N) {
    int i = blockIdx.x * blockDim.x + threadIdx.x;
    if (i < E) {
        int dst = EDST[i];
        int pos = atomicAdd(&g_CUR[dst], 1);
        g_CSRC[pos] = ESRC[i];
    } else if (i < E + N) {
        int n = i - E;
        int pos = atomicAdd(&g_CUR[n], 1);
        g_CSRC[pos] = n;
    }
}

// =====================================================================
// GEMM: XH[N,256] = X[N,64] @ W[64,256], fused a_src/a_dst dot epilogue.
// blockIdx.y == head h (cols [64h, 64h+64)).
// =====================================================================
__global__ void gemm_kernel(const float* __restrict__ X, const float* __restrict__ W,
                            const float* __restrict__ asrc, const float* __restrict__ adst,
                            int N) {
    __shared__ float xs[64][65];
    __shared__ float ws[64][65];
    int m0 = blockIdx.x * 64;
    int h = blockIdx.y;
    int j0 = h * 64;
    int tid = threadIdx.x;
    for (int i = tid; i < 64 * 64; i += 256) {
        int r = i >> 6, k = i & 63;
        int row = m0 + r;
        xs[r][k] = (row < N) ? X[row * 64 + k] : 0.0f;
        ws[r][k] = W[r * HC + j0 + k];   // ws[k][j]
    }
    __syncthreads();
    int tx = tid & 15, ty = tid >> 4;
    float acc[4][4];
#pragma unroll
    for (int i = 0; i < 4; i++)
#pragma unroll
        for (int j = 0; j < 4; j++) acc[i][j] = 0.0f;
#pragma unroll 8
    for (int k = 0; k < 64; k++) {
        float a[4], b[4];
#pragma unroll
        for (int i = 0; i < 4; i++) a[i] = xs[ty * 4 + i][k];
#pragma unroll
        for (int j = 0; j < 4; j++) b[j] = ws[k][tx * 4 + j];
#pragma unroll
        for (int i = 0; i < 4; i++)
#pragma unroll
            for (int j = 0; j < 4; j++) acc[i][j] += a[i] * b[j];
    }
    // store XH
#pragma unroll
    for (int i = 0; i < 4; i++) {
        int row = m0 + ty * 4 + i;
        if (row < N) {
#pragma unroll
            for (int j = 0; j < 4; j++)
                g_XH[(size_t)row * HC + j0 + tx * 4 + j] = acc[i][j];
        }
    }
    // fused epilogue: als/ald = dot(acc_row, asrc/adst[h])
    float a_s[4], a_d[4];
#pragma unroll
    for (int j = 0; j < 4; j++) {
        a_s[j] = asrc[j0 + tx * 4 + j];
        a_d[j] = adst[j0 + tx * 4 + j];
    }
#pragma unroll
    for (int i = 0; i < 4; i++) {
        float ss = 0.0f, sd = 0.0f;
#pragma unroll
        for (int j = 0; j < 4; j++) {
            ss += acc[i][j] * a_s[j];
            sd += acc[i][j] * a_d[j];
        }
        // reduce across the 16 tx lanes (contiguous within half-warp)
#pragma unroll
        for (int o = 8; o > 0; o >>= 1) {
            ss += __shfl_xor_sync(0xffffffffu, ss, o);
            sd += __shfl_xor_sync(0xffffffffu, sd, o);
        }
        int row = m0 + ty * 4 + i;
        if (tx == 0 && row < N) {
            g_ALS[row * 4 + h] = ss;
            g_ALD[row * 4 + h] = sd;
        }
    }
}

// =====================================================================
// Fused per-node GAT aggregation: softmax (max / exp-sum) + weighted gather
// + head mean + bias. One 64-thread block per destination node. No atomics.
// =====================================================================
__global__ __launch_bounds__(64) void gat_aggregate_kernel(
        const float* __restrict__ bias, float* __restrict__ SAV, int N) {
    int n = blockIdx.x;
    int t = threadIdx.x;
    int lane = t & 31, w = t >> 5;
    int base = g_ROWPTR[n];
    int deg  = g_ROWPTR[n + 1] - base;

    __shared__ float shm[8];
    __shared__ float shs[8];
    __shared__ float4 xsh[32];

    float4 ald = *(const float4*)(g_ALD + n * 4);

    // ---- phase A: per-head segment max ----
    float m0 = -1e30f, m1 = -1e30f, m2 = -1e30f, m3 = -1e30f;
    for (int i = t; i < deg; i += 64) {
        int s = g_CSRC[base + i];
        float4 a = *(const float4*)(g_ALS + s * 4);
        float e0 = a.x + ald.x; e0 = e0 > 0.0f ? e0 : 0.2f * e0; m0 = fmaxf(m0, e0);
        float e1 = a.y + ald.y; e1 = e1 > 0.0f ? e1 : 0.2f * e1; m1 = fmaxf(m1, e1);
        float e2 = a.z + ald.z; e2 = e2 > 0.0f ? e2 : 0.2f * e2; m2 = fmaxf(m2, e2);
        float e3 = a.w + ald.w; e3 = e3 > 0.0f ? e3 : 0.2f * e3; m3 = fmaxf(m3, e3);
    }
#pragma unroll
    for (int o = 16; o > 0; o >>= 1) {
        m0 = fmaxf(m0, __shfl_xor_sync(0xffffffffu, m0, o));
        m1 = fmaxf(m1, __shfl_xor_sync(0xffffffffu, m1, o));
        m2 = fmaxf(m2, __shfl_xor_sync(0xffffffffu, m2, o));
        m3 = fmaxf(m3, __shfl_xor_sync(0xffffffffu, m3, o));
    }
    if (lane == 0) { shm[w * 4 + 0] = m0; shm[w * 4 + 1] = m1; shm[w * 4 + 2] = m2; shm[w * 4 + 3] = m3; }
    __syncthreads();
    m0 = fmaxf(shm[0], shm[4]); m1 = fmaxf(shm[1], shm[5]);
    m2 = fmaxf(shm[2], shm[6]); m3 = fmaxf(shm[3], shm[7]);

    // ---- phase B: p = exp(e - m), per-head sum; stash p in CSR-order buffer ----
    float s0 = 0.0f, s1 = 0.0f, s2 = 0.0f, s3 = 0.0f;
    for (int i = t; i < deg; i += 64) {
        int s = g_CSRC[base + i];
        float4 a = *(const float4*)(g_ALS + s * 4);
        float e0 = a.x + ald.x; e0 = e0 > 0.0f ? e0 : 0.2f * e0;
        float e1 = a.y + ald.y; e1 = e1 > 0.0f ? e1 : 0.2f * e1;
        float e2 = a.z + ald.z; e2 = e2 > 0.0f ? e2 : 0.2f * e2;
        float e3 = a.w + ald.w; e3 = e3 > 0.0f ? e3 : 0.2f * e3;
        float p0 = __expf(e0 - m0); s0 += p0;
        float p1 = __expf(e1 - m1); s1 += p1;
        float p2 = __expf(e2 - m2); s2 += p2;
        float p3 = __expf(e3 - m3); s3 += p3;
        *(float4*)(g_EBUF + (size_t)(base + i) * 4) = make_float4(p0, p1, p2, p3);
    }
#pragma unroll
    for (int o = 16; o > 0; o >>= 1) {
        s0 += __shfl_xor_sync(0xffffffffu, s0, o);
        s1 += __shfl_xor_sync(0xffffffffu, s1, o);
        s2 += __shfl_xor_sync(0xffffffffu, s2, o);
        s3 += __shfl_xor_sync(0xffffffffu, s3, o);
    }
    if (lane == 0) { shs[w * 4 + 0] = s0; shs[w * 4 + 1] = s1; shs[w * 4 + 2] = s2; shs[w * 4 + 3] = s3; }
    __syncthreads();
    s0 = shs[0] + shs[4]; s1 = shs[1] + shs[5];
    s2 = shs[2] + shs[6]; s3 = shs[3] + shs[7];
    float rc0 = 0.25f / (s0 + 1e-16f);
    float rc1 = 0.25f / (s1 + 1e-16f);
    float rc2 = 0.25f / (s2 + 1e-16f);
    float rc3 = 0.25f / (s3 + 1e-16f);

    // ---- phase C: weighted gather. thread t owns bytes [t*16, t*16+16) of the
    //      256-float row => head hh = t>>4, channels cb..cb+3. ----
    int hh = t >> 4;
    float rc = (hh == 0) ? rc0 : (hh == 1) ? rc1 : (hh == 2) ? rc2 : rc3;
    float4 acc = make_float4(0.0f, 0.0f, 0.0f, 0.0f);
    for (int i = 0; i < deg; i++) {
        int s = g_CSRC[base + i];                                   // broadcast
        float4 p = *(const float4*)(g_EBUF + (size_t)(base + i) * 4); // broadcast
        float ph = (hh == 0) ? p.x : (hh == 1) ? p.y : (hh == 2) ? p.z : p.w;
        float4 rv = *(const float4*)(g_XH + (size_t)s * HC + t * 4);  // coalesced 16B
        acc.x += ph * rv.x;
        acc.y += ph * rv.y;
        acc.z += ph * rv.z;
        acc.w += ph * rv.w;
    }
    acc.x *= rc; acc.y *= rc; acc.z *= rc; acc.w *= rc;

    // reduce over heads: lane^16 pairs heads within each warp, smem pairs warps
    acc.x += __shfl_xor_sync(0xffffffffu, acc.x, 16);
    acc.y += __shfl_xor_sync(0xffffffffu, acc.y, 16);
    acc.z += __shfl_xor_sync(0xffffffffu, acc.z, 16);
    acc.w += __shfl_xor_sync(0xffffffffu, acc.w, 16);
    if (lane < 16) xsh[w * 16 + lane] = acc;
    __syncthreads();
    if (t < 16) {
        float4 a = xsh[t];
        float4 b = xsh[16 + t];
        float4 bi = *(const float4*)(bias + t * 4);
        float4 o;
        o.x = a.x + b.x + bi.x;
        o.y = a.y + b.y + bi.y;
        o.z = a.z + b.z + bi.z;
        o.w = a.w + b.w + bi.w;
        *(float4*)(SAV + (size_t)n * 64 + t * 4) = o;
    }
}

// =====================================================================
// BatchNorm
// =====================================================================
__global__ void zero_bns_kernel() {
    int i = threadIdx.x;
    if (i < 128) g_BNS[i] = 0.0;
}

__global__ void stats_kernel(const float* __restrict__ SAV, int N) {
    __shared__ float s1[64], s2[64];
    if (threadIdx.x < 64) { s1[threadIdx.x] = 0.0f; s2[threadIdx.x] = 0.0f; }
    __syncthreads();
    int c = threadIdx.x & 63;
    float ls = 0.0f, lq = 0.0f;
    int total = N * 64;
    int stride = gridDim.x * blockDim.x;   // multiple of 64
    for (int i = blockIdx.x * blockDim.x + threadIdx.x; i < total; i += stride) {
        float v = SAV[i];
        ls += v;
        lq += v * v;
    }
    atomicAdd(&s1[c], ls);
    atomicAdd(&s2[c], lq);
    __syncthreads();
    if (threadIdx.x < 64) {
        atomicAdd(&g_BNS[threadIdx.x], (double)s1[threadIdx.x]);
        atomicAdd(&g_BNS[64 + threadIdx.x], (double)s2[threadIdx.x]);
    }
}

__global__ void bn_param_kernel(const float* __restrict__ gamma, const float* __restrict__ beta, int N) {
    int c = threadIdx.x;
    if (c >= 64) return;
    double mean = g_BNS[c] / (double)N;
    double var = g_BNS[64 + c] / (double)N - mean * mean;
    float sc = gamma[c] * rsqrtf((float)(var + 1e-5));
    g_SCALE[c] = sc;
    g_SHIFT[c] = beta[c] - (float)mean * sc;
}

__global__ void bn_relu_kernel(const float* __restrict__ SAV, float* __restrict__ OUT, int N) {
    int i = blockIdx.x * blockDim.x + threadIdx.x;
    if (i >= N * 64) return;
    int c = i & 63;
    float v = g_SCALE[c] * SAV[i] + g_SHIFT[c];
    OUT[i] = v > 0.0f ? v : 0.0f;
}

// =====================================================================
// host launch
// =====================================================================
static void run_layer(const float* xin,
                      const float* W, const float* asrc, const float* adst,
                      const float* bias, const float* gamma, const float* beta,
                      float* SAV, float* OUT, int N, int E) {
    dim3 gg((N + 63) / 64, HEADS);
    gemm_kernel<<<gg, 256>>>(xin, W, asrc, adst, N);
    gat_aggregate_kernel<<<N, 64>>>(bias, SAV, N);
    zero_bns_kernel<<<1, 128>>>();
    stats_kernel<<<1024, 256>>>(SAV, N);
    bn_param_kernel<<<1, 64>>>(gamma, beta, N);
    bn_relu_kernel<<<(N * 64 + 255) / 256, 256>>>(SAV, OUT, N);
}

extern "C" void kernel_launch(void* const* d_in, const int* in_sizes, int n_in,
                              void* d_out, int out_size) {
    const float* x  = (const float*)d_in[0];
    const int*   EI = (const int*)d_in[1];   // int32 node ids
    // d_in[2] = edge_weight (ignored, edge_dim=None)
    const float* W0 = (const float*)d_in[3];
    const float* as0 = (const float*)d_in[4];
    const float* ad0 = (const float*)d_in[5];
    const float* b0 = (const float*)d_in[6];
    const float* g0 = (const float*)d_in[7];
    const float* be0 = (const float*)d_in[8];
    const float* W1 = (const float*)d_in[9];
    const float* as1 = (const float*)d_in[10];
    const float* ad1 = (const float*)d_in[11];
    const float* b1 = (const float*)d_in[12];
    const float* g1 = (const float*)d_in[13];
    const float* be1 = (const float*)d_in[14];

    int N = in_sizes[0] / C_IN;
    int E = in_sizes[1] / 2;
    if (N > MAXN) N = MAXN;
    if (E > MAXE) E = MAXE;

    const int* ESRC = EI;        // edge_index[0]
    const int* EDST = EI + E;    // edge_index[1]

    float* out = (float*)d_out;           // [0 : N*64)        -> x (post bn+relu)
    float* saved = out + (size_t)N * 64;  // [N*64 : 2*N*64)   -> layer-2 pre-BN

    float* dSAV1;
    float* dH1;
    cudaGetSymbolAddress((void**)&dSAV1, g_SAV1);
    cudaGetSymbolAddress((void**)&dH1, g_H1);

    // CSR build (structure shared by both layers)
    deg_init_kernel<<<(N + 255) / 256, 256>>>(N);
    deg_count_kernel<<<(E + 255) / 256, 256>>>(EDST, E);
    scan_kernel<<<1, 1024>>>(N);
    fill_kernel<<<(E + N + 255) / 256, 256>>>(ESRC, EDST, E, N);

    // layer 0
    run_layer(x, W0, as0, ad0, b0, g0, be0, dSAV1, dH1, N, E);
    // layer 1: saved goes straight into d_out second half, normalized into first half
    run_layer(dH1, W1, as1, ad1, b1, g1, be1, saved, out, N, E);
}